// round 16
// baseline (speedup 1.0000x reference)
#include <cuda_runtime.h>
#include <cuda_fp16.h>
#include <cstdint>

#define THREADS 256
#define CTA_M   64
#define HROW    128                      // H row stride (words); 64 rows at offset 0
#define XSLOTW  2048                     // X slot: 64 rows x 32 words (8KB); 4 slots = H region
#define XSLOTB  (XSLOTW * 4)
#define SMEM_BYTES 34816                 // 32KB H/X + epilogue spill (64*132*4=33792)

// packed fragment-major fp16 weights:
// Wp[((n*(K/16) + gi)*4 + c)*4 + j] = W[k][n],  k = gi*16 + c*2 + (j>>1)*8 + (j&1)
__device__ __half g_W1p[256 * 512];
__device__ __half g_W2p[256 * 256];
__device__ __half g_W3p[128 * 256];

__device__ __forceinline__ uint32_t smem_u32(const void* p) {
    uint32_t a;
    asm("{ .reg .u64 t; cvta.to.shared.u64 t, %1; cvt.u32.u64 %0, t; }" : "=r"(a) : "l"(p));
    return a;
}
__device__ __forceinline__ float softplus_f(float x) {
    return (x > 20.0f) ? x : __logf(1.0f + __expf(x));
}
__device__ __forceinline__ uint32_t pack_h2(float lo, float hi) {
    __half2 h = __halves2half2(__float2half_rn(lo), __float2half_rn(hi));
    return *(uint32_t*)&h;
}
__device__ __forceinline__ void mma16(float* c, uint32_t a0, uint32_t a1,
                                      uint32_t a2, uint32_t a3,
                                      uint32_t b0, uint32_t b1) {
    asm volatile(
        "mma.sync.aligned.m16n8k16.row.col.f32.f16.f16.f32 "
        "{%0,%1,%2,%3}, {%4,%5,%6,%7}, {%8,%9}, {%0,%1,%2,%3};\n"
        : "+f"(c[0]), "+f"(c[1]), "+f"(c[2]), "+f"(c[3])
        : "r"(a0), "r"(a1), "r"(a2), "r"(a3), "r"(b0), "r"(b1));
}
__device__ __forceinline__ void ldsm4(uint32_t* r, uint32_t addr) {
    asm volatile("ldmatrix.sync.aligned.m8n8.x4.shared.b16 {%0,%1,%2,%3}, [%4];"
        : "=r"(r[0]), "=r"(r[1]), "=r"(r[2]), "=r"(r[3]) : "r"(addr));
}

// ---- GEMM over one 64-K chunk: A via ldmatrix from smem, B via direct LDG.64
// from packed gmem (1-gi-ahead register prefetch). KD16 = K/16 of the layer.
template <int NTP, int KD16>
__device__ __forceinline__ void gemm64_ldgb(float acc[4][2 * NTP][4],
                                            uint32_t aBase, int arowB, int aub,
                                            const uint2* __restrict__ bp,
                                            int gi0, int lane) {
    int rw = lane & 7;
    int duA = (lane >> 4) & 1;
    uint32_t aL = aBase + (uint32_t)((((lane >> 3) & 1) * 8 + rw) * arowB);
    uint2 breg[NTP][2];
#pragma unroll
    for (int ntp = 0; ntp < NTP; ntp++) {
        breg[ntp][0] = bp[((ntp * 16 + 0) * KD16 + gi0) * 4];
        breg[ntp][1] = bp[((ntp * 16 + 8) * KD16 + gi0) * 4];
    }
#pragma unroll
    for (int gi = 0; gi < 4; gi++) {
        uint2 bnx[NTP][2];
        if (gi < 3) {
#pragma unroll
            for (int ntp = 0; ntp < NTP; ntp++) {
                bnx[ntp][0] = bp[((ntp * 16 + 0) * KD16 + gi0 + gi + 1) * 4];
                bnx[ntp][1] = bp[((ntp * 16 + 8) * KD16 + gi0 + gi + 1) * 4];
            }
        }
        uint32_t uA = (uint32_t)(aub + ((2 * gi + duA) ^ rw)) << 4;
        uint32_t a[4][4];
#pragma unroll
        for (int mt = 0; mt < 4; mt++)
            ldsm4(a[mt], aL + mt * 16 * arowB + uA);
#pragma unroll
        for (int ntp = 0; ntp < NTP; ntp++) {
#pragma unroll
            for (int mt = 0; mt < 4; mt++) {
                mma16(acc[mt][2 * ntp],     a[mt][0], a[mt][1], a[mt][2], a[mt][3],
                      breg[ntp][0].x, breg[ntp][0].y);
                mma16(acc[mt][2 * ntp + 1], a[mt][0], a[mt][1], a[mt][2], a[mt][3],
                      breg[ntp][1].x, breg[ntp][1].y);
            }
        }
        if (gi < 3) {
#pragma unroll
            for (int ntp = 0; ntp < NTP; ntp++) {
                breg[ntp][0] = bnx[ntp][0];
                breg[ntp][1] = bnx[ntp][1];
            }
        }
    }
}

// ---- X staging split: LDG (hoisted) / STS (8-unit swizzle, R13-verified) ----
__device__ __forceinline__ void x_ldg(float4 xv[4], const float* p, int kc, int tid) {
    int q = tid & 3;
    int off = ((kc * 64) & 127) + q * 16;
    xv[0] = *(const float4*)(p + off);
    xv[1] = *(const float4*)(p + off + 4);
    xv[2] = *(const float4*)(p + off + 8);
    xv[3] = *(const float4*)(p + off + 12);
}
__device__ __forceinline__ void x_sts(uint32_t* x, const float4 xv[4], int tid) {
    int row = tid >> 2, q = tid & 3;
    uint4 o1 = make_uint4(pack_h2(xv[0].x, xv[0].y), pack_h2(xv[0].z, xv[0].w),
                          pack_h2(xv[1].x, xv[1].y), pack_h2(xv[1].z, xv[1].w));
    uint4 o2 = make_uint4(pack_h2(xv[2].x, xv[2].y), pack_h2(xv[2].z, xv[2].w),
                          pack_h2(xv[3].x, xv[3].y), pack_h2(xv[3].z, xv[3].w));
    int rm = row & 7;
    *(uint4*)(x + row * 32 + (((2 * q) ^ rm) << 2)) = o1;
    *(uint4*)(x + row * 32 + (((2 * q + 1) ^ rm) << 2)) = o2;
}

// ---- epilogue layers 1/2: bias + softplus -> half2 into H (R13-verified) ----
template <int NT>
__device__ __forceinline__ void epi_h(float acc[4][NT][4], uint32_t* smw,
                                      const float* __restrict__ bias,
                                      int n0, int g, int t) {
#pragma unroll
    for (int nt = 0; nt < NT; nt++) {
        int c = n0 + nt * 8 + 2 * t;
        float bb0 = __ldg(bias + c);
        float bb1 = __ldg(bias + c + 1);
        int uu = (n0 >> 3) + nt;
        int w = ((uu ^ g) << 2) + t;
#pragma unroll
        for (int mt = 0; mt < 4; mt++) {
            int r = mt * 16 + g;
            smw[r * HROW + w] =
                pack_h2(softplus_f(acc[mt][nt][0] + bb0), softplus_f(acc[mt][nt][1] + bb1));
            smw[(r + 8) * HROW + w] =
                pack_h2(softplus_f(acc[mt][nt][2] + bb0), softplus_f(acc[mt][nt][3] + bb1));
        }
    }
}

// ---- prepass: W [K][N] -> fragment-packed Wp ----
__global__ void prep_wp(const float* __restrict__ W, __half* __restrict__ Wp,
                        int K, int N) {
    int i = blockIdx.x * blockDim.x + threadIdx.x;   // over N * (K/16) * 4
    int kd16 = K >> 4;
    int total = N * kd16 * 4;
    if (i >= total) return;
    int c = i & 3;
    int gi = (i >> 2) % kd16;
    int n = i / (kd16 * 4);
    int k0 = gi * 16 + c * 2;
    __half h0 = __float2half_rn(W[(long)k0 * N + n]);
    __half h1 = __float2half_rn(W[(long)(k0 + 1) * N + n]);
    __half h2 = __float2half_rn(W[(long)(k0 + 8) * N + n]);
    __half h3 = __float2half_rn(W[(long)(k0 + 9) * N + n]);
    __half2 lo = __halves2half2(h0, h1);
    __half2 hi = __halves2half2(h2, h3);
    uint2 v = make_uint2(*(uint32_t*)&lo, *(uint32_t*)&hi);
    *(uint2*)(Wp + (long)i * 4) = v;
}

__global__ void __launch_bounds__(THREADS, 2)
edge_mlp_v16(const float* __restrict__ src, const float* __restrict__ dstp,
             const float* __restrict__ ea, const float* __restrict__ u,
             const void* __restrict__ batch,
             const float* __restrict__ b1, const float* __restrict__ b2,
             const float* __restrict__ b3,
             float* __restrict__ out) {
    extern __shared__ uint32_t smw[];
    uint32_t sbyte = smem_u32(smw);

    int tid = threadIdx.x;
    int wid = tid >> 5;
    int lane = tid & 31;
    int g = lane >> 2;
    int t = lane & 3;
    int n0 = wid * 32;
    int n3 = wid * 16;
    long e0 = (long)blockIdx.x * CTA_M;

    // lane-resolved packed-B pointers (uint2 units; +lane&3 folds fragment column)
    const uint2* bp1 = (const uint2*)g_W1p + (size_t)(n0 + (lane >> 2)) * 32 * 4 + (lane & 3);
    const uint2* bp2 = (const uint2*)g_W2p + (size_t)(n0 + (lane >> 2)) * 16 * 4 + (lane & 3);
    const uint2* bp3 = (const uint2*)g_W3p + (size_t)(n3 + (lane >> 2)) * 16 * 4 + (lane & 3);

    __shared__ int b64s;
    if (tid == 0) {
        const long long* p = (const long long*)batch;
        int f = 1;
        for (int i = 0; i < 16; i++) { long long v = p[i]; if (v < 0 || v >= 64) f = 0; }
        b64s = f;
    }
    __syncthreads();
    int b64 = b64s;

    // per-thread X source pointers, gather index resolved once
    int xrow = tid >> 2;
    const float* pseg0 = src  + (e0 + xrow) * 128;
    const float* pseg1 = dstp + (e0 + xrow) * 128;
    const float* pseg2 = ea   + (e0 + xrow) * 128;
    long bi = b64 ? (long)((const long long*)batch)[e0 + xrow]
                  : (long)((const int*)batch)[e0 + xrow];
    const float* pseg3 = u + bi * 128;

    float acc[4][4][4];
#pragma unroll
    for (int a = 0; a < 4; a++)
#pragma unroll
        for (int b = 0; b < 4; b++)
#pragma unroll
            for (int c = 0; c < 4; c++) acc[a][b][c] = 0.0f;

    // ---- prolog: X chunks 0,1 -> slots 0,1 ----
    {
        float4 xv[4];
        x_ldg(xv, pseg0, 0, tid);
        x_sts(smw, xv, tid);
        x_ldg(xv, pseg0, 1, tid);
        x_sts(smw + XSLOTW, xv, tid);
    }
    __syncthreads();

    // ============== Layer 1: K=512 (8 chunks of 64), ONE barrier/chunk =====
#pragma unroll 1
    for (int kc = 0; kc < 8; kc++) {
        if (kc > 0) __syncthreads();      // gemm(kc-1) done; slots {kc,kc+1} live
        float4 xv[4];
        bool pfx = (kc < 6);
        if (pfx) {
            int kn = kc + 2, seg = kn >> 1;
            const float* p = (seg == 0) ? pseg0 : (seg == 1) ? pseg1
                           : (seg == 2) ? pseg2 : pseg3;
            x_ldg(xv, p, kn, tid);        // latency hides under gemm
        }
        gemm64_ldgb<2, 32>(acc, sbyte + (uint32_t)((kc & 3) * XSLOTB), 128, 0,
                           bp1, kc * 4, lane);
        if (pfx) x_sts(smw + ((kc + 2) & 3) * XSLOTW, xv, tid);
    }
    __syncthreads();                      // all layer-1 gemms + X reads done
    epi_h<4>(acc, smw, b1, n0, g, t);
    __syncthreads();                      // publish H1

    // ============== Layer 2: K=256 (4 chunks), NO barriers ================
#pragma unroll
    for (int a = 0; a < 4; a++)
#pragma unroll
        for (int b = 0; b < 4; b++)
#pragma unroll
            for (int c = 0; c < 4; c++) acc[a][b][c] = 0.0f;
#pragma unroll 1
    for (int kc = 0; kc < 4; kc++)
        gemm64_ldgb<2, 16>(acc, sbyte, 512, 8 * kc, bp2, kc * 4, lane);
    __syncthreads();                      // all H1 reads done
    epi_h<4>(acc, smw, b2, n0, g, t);
    __syncthreads();                      // publish H2

    // ============== Layer 3: K=256 (4 chunks), N=128, NO barriers ==========
    float acc3[4][2][4];
#pragma unroll
    for (int a = 0; a < 4; a++)
#pragma unroll
        for (int b = 0; b < 2; b++)
#pragma unroll
            for (int c = 0; c < 4; c++) acc3[a][b][c] = 0.0f;
#pragma unroll 1
    for (int kc = 0; kc < 4; kc++)
        gemm64_ldgb<1, 16>(acc3, sbyte, 512, 8 * kc, bp3, kc * 4, lane);
    __syncthreads();                      // all H2 reads done

    // ---- output epilogue: f32 scratch (stride 132) -> coalesced STG ----
    float* fH = (float*)smw;
#pragma unroll
    for (int nt = 0; nt < 2; nt++) {
        int c = n3 + nt * 8 + 2 * t;
        float bb0 = __ldg(b3 + c);
        float bb1 = __ldg(b3 + c + 1);
#pragma unroll
        for (int mt = 0; mt < 4; mt++) {
            int r = mt * 16 + g;
            *(float2*)(fH + r * 132 + c) =
                make_float2(acc3[mt][nt][0] + bb0, acc3[mt][nt][1] + bb1);
            *(float2*)(fH + (r + 8) * 132 + c) =
                make_float2(acc3[mt][nt][2] + bb0, acc3[mt][nt][3] + bb1);
        }
    }
    __syncthreads();
#pragma unroll
    for (int it = 0; it < 8; it++) {
        int task = tid + it * THREADS;
        int row = task >> 5, c4 = task & 31;
        *(float4*)(out + (e0 + row) * 128 + c4 * 4) =
            *(const float4*)(fH + row * 132 + c4 * 4);
    }
}

extern "C" void kernel_launch(void* const* d_in, const int* in_sizes, int n_in,
                              void* d_out, int out_size) {
    const float* src  = (const float*)d_in[0];
    const float* dstp = (const float*)d_in[1];
    const float* ea   = (const float*)d_in[2];
    const float* u    = (const float*)d_in[3];
    const void*  bat  = (const void*)d_in[4];
    const float* W1   = (const float*)d_in[5];
    const float* b1   = (const float*)d_in[6];
    const float* W2   = (const float*)d_in[7];
    const float* b2   = (const float*)d_in[8];
    const float* W3   = (const float*)d_in[9];
    const float* b3   = (const float*)d_in[10];
    float* out = (float*)d_out;

    cudaFuncSetAttribute(edge_mlp_v16,
                         cudaFuncAttributeMaxDynamicSharedMemorySize, SMEM_BYTES);

    __half *w1p, *w2p, *w3p;
    cudaGetSymbolAddress((void**)&w1p, g_W1p);
    cudaGetSymbolAddress((void**)&w2p, g_W2p);
    cudaGetSymbolAddress((void**)&w3p, g_W3p);
    prep_wp<<<(256 * 32 * 4 + 255) / 256, 256>>>(W1, w1p, 512, 256);
    prep_wp<<<(256 * 16 * 4 + 255) / 256, 256>>>(W2, w2p, 256, 256);
    prep_wp<<<(128 * 16 * 4 + 255) / 256, 256>>>(W3, w3p, 256, 128);

    const int n_edges = in_sizes[4];
    const int grid = n_edges / CTA_M;   // 6250
    edge_mlp_v16<<<grid, THREADS, SMEM_BYTES>>>(src, dstp, ea, u, bat,
                                                b1, b2, b3, out);
}

// round 17
// speedup vs baseline: 1.0973x; 1.0973x over previous
#include <cuda_runtime.h>
#include <cuda_fp16.h>
#include <cstdint>

#define THREADS 256
#define CTA_M   64
#define HROW    128                     // H row stride (words); 64 rows at offset 0
#define XSLOTW  2048                    // X slot: 64 rows x 32 words (one 64-K chunk)
#define WOFFW   8192
#define WSLOTW  8192                    // W slot: 256 rows x 32 words
#define WSLOTB  (WSLOTW * 4)
#define SMEM_WORDS (WOFFW + 2 * WSLOTW) // 24576
#define SMEM_BYTES (SMEM_WORDS * 4)     // 98304 (2 CTAs/SM)

// pre-transposed fp16 weights, natural K-major: Wt[n][k]
__device__ __half g_W1t[256 * 512];
__device__ __half g_W2t[256 * 256];
__device__ __half g_W3t[128 * 256];

__device__ __forceinline__ uint32_t smem_u32(const void* p) {
    uint32_t a;
    asm("{ .reg .u64 t; cvta.to.shared.u64 t, %1; cvt.u32.u64 %0, t; }" : "=r"(a) : "l"(p));
    return a;
}
__device__ __forceinline__ float softplus_f(float x) {
    return (x > 20.0f) ? x : __logf(1.0f + __expf(x));
}
__device__ __forceinline__ uint32_t pack_h2(float lo, float hi) {
    __half2 h = __halves2half2(__float2half_rn(lo), __float2half_rn(hi));
    return *(uint32_t*)&h;
}
__device__ __forceinline__ void mma16(float* c, uint32_t a0, uint32_t a1,
                                      uint32_t a2, uint32_t a3,
                                      uint32_t b0, uint32_t b1) {
    asm volatile(
        "mma.sync.aligned.m16n8k16.row.col.f32.f16.f16.f32 "
        "{%0,%1,%2,%3}, {%4,%5,%6,%7}, {%8,%9}, {%0,%1,%2,%3};\n"
        : "+f"(c[0]), "+f"(c[1]), "+f"(c[2]), "+f"(c[3])
        : "r"(a0), "r"(a1), "r"(a2), "r"(a3), "r"(b0), "r"(b1));
}
__device__ __forceinline__ void ldsm4(uint32_t* r, uint32_t addr) {
    asm volatile("ldmatrix.sync.aligned.m8n8.x4.shared.b16 {%0,%1,%2,%3}, [%4];"
        : "=r"(r[0]), "=r"(r[1]), "=r"(r[2]), "=r"(r[3]) : "r"(addr));
}
__device__ __forceinline__ void cp16(uint32_t dst, const void* src) {
    asm volatile("cp.async.cg.shared.global [%0], [%1], 16;" :: "r"(dst), "l"(src) : "memory");
}
#define CP_COMMIT() asm volatile("cp.async.commit_group;" ::: "memory")
#define CP_WAIT1()  asm volatile("cp.async.wait_group 1;" ::: "memory")
#define CP_WAIT0()  asm volatile("cp.async.wait_group 0;" ::: "memory")

// ---- GEMM over one 64-K chunk via ldmatrix (R13-verified, unchanged) ----
template <int NTP>
__device__ __forceinline__ void gemm64(float acc[4][2 * NTP][4],
                                       uint32_t aBase, int arowB, int aub,
                                       uint32_t bBase, int lane) {
    int rw = lane & 7;
    int duA = (lane >> 4) & 1;
    int duB = (lane >> 3) & 1;
    uint32_t aL = aBase + (uint32_t)((((lane >> 3) & 1) * 8 + rw) * arowB);
#pragma unroll
    for (int gi = 0; gi < 4; gi++) {
        uint32_t uA = (uint32_t)(aub + ((2 * gi + duA) ^ rw)) << 4;
        uint32_t a[4][4];
#pragma unroll
        for (int mt = 0; mt < 4; mt++)
            ldsm4(a[mt], aL + mt * 16 * arowB + uA);
        uint32_t uB = (uint32_t)((2 * gi + duB) ^ rw) << 4;
#pragma unroll
        for (int ntp = 0; ntp < NTP; ntp++) {
            uint32_t b[4];
            ldsm4(b, bBase + ntp * (16 * 128) + uB);
#pragma unroll
            for (int mt = 0; mt < 4; mt++) {
                mma16(acc[mt][2 * ntp],     a[mt][0], a[mt][1], a[mt][2], a[mt][3], b[0], b[1]);
                mma16(acc[mt][2 * ntp + 1], a[mt][0], a[mt][1], a[mt][2], a[mt][3], b[2], b[3]);
            }
        }
    }
}

// ---- X staging split: LDG (hoisted above gemm) / STS (R13-verified) ----
__device__ __forceinline__ void x_ldg(float4 xv[4], const float* p, int kc, int tid) {
    int q = tid & 3;
    int off = ((kc * 64) & 127) + q * 16;
    xv[0] = *(const float4*)(p + off);
    xv[1] = *(const float4*)(p + off + 4);
    xv[2] = *(const float4*)(p + off + 8);
    xv[3] = *(const float4*)(p + off + 12);
}
__device__ __forceinline__ void x_sts(uint32_t* x, const float4 xv[4], int tid) {
    int row = tid >> 2, q = tid & 3;
    uint4 o1 = make_uint4(pack_h2(xv[0].x, xv[0].y), pack_h2(xv[0].z, xv[0].w),
                          pack_h2(xv[1].x, xv[1].y), pack_h2(xv[1].z, xv[1].w));
    uint4 o2 = make_uint4(pack_h2(xv[2].x, xv[2].y), pack_h2(xv[2].z, xv[2].w),
                          pack_h2(xv[3].x, xv[3].y), pack_h2(xv[3].z, xv[3].w));
    int rm = row & 7;
    *(uint4*)(x + row * 32 + (((2 * q) ^ rm) << 2)) = o1;
    *(uint4*)(x + row * 32 + (((2 * q + 1) ^ rm) << 2)) = o2;
}

// ---- W staging: 64-K chunk via cp.async (16B units), swizzled dst ----
template <int NROWS, int KFULL>
__device__ __forceinline__ void stage_w(uint32_t wbase_byte, const __half* __restrict__ Wt,
                                        int kc, int tid) {
#pragma unroll
    for (int it = 0; it < (NROWS * 8) / THREADS; it++) {
        int task = tid + it * THREADS;
        int row = task >> 3, q = task & 7;
        uint32_t dst = wbase_byte + (row * 32 + ((q ^ (row & 7)) << 2)) * 4;
        cp16(dst, Wt + (long)row * KFULL + kc * 64 + q * 8);
    }
}

// ---- epilogue layers 1/2: bias + softplus -> half2 into H (R13) ----
template <int NT>
__device__ __forceinline__ void epi_h(float acc[4][NT][4], uint32_t* smw,
                                      const float* __restrict__ bias,
                                      int n0, int g, int t) {
#pragma unroll
    for (int nt = 0; nt < NT; nt++) {
        int c = n0 + nt * 8 + 2 * t;
        float bb0 = __ldg(bias + c);
        float bb1 = __ldg(bias + c + 1);
        int uu = (n0 >> 3) + nt;
        int w = ((uu ^ g) << 2) + t;
#pragma unroll
        for (int mt = 0; mt < 4; mt++) {
            int r = mt * 16 + g;
            smw[r * HROW + w] =
                pack_h2(softplus_f(acc[mt][nt][0] + bb0), softplus_f(acc[mt][nt][1] + bb1));
            smw[(r + 8) * HROW + w] =
                pack_h2(softplus_f(acc[mt][nt][2] + bb0), softplus_f(acc[mt][nt][3] + bb1));
        }
    }
}

// ---- prepass: W [K][N] -> Wt [N][K] fp16 ----
__global__ void prep_w(const float* __restrict__ W, __half* __restrict__ Wt,
                       int K, int N) {
    __shared__ float tile[32][33];
    int kb = blockIdx.x * 32, nb = blockIdx.y * 32;
    int tx = threadIdx.x, ty = threadIdx.y;
    for (int i = ty; i < 32; i += 8)
        tile[i][tx] = W[(long)(kb + i) * N + nb + tx];
    __syncthreads();
    for (int i = ty; i < 32; i += 8)
        Wt[(long)(nb + i) * K + kb + tx] = __float2half_rn(tile[tx][i]);
}

__global__ void __launch_bounds__(THREADS, 2)
edge_mlp_v17(const float* __restrict__ src, const float* __restrict__ dstp,
             const float* __restrict__ ea, const float* __restrict__ u,
             const void* __restrict__ batch,
             const float* __restrict__ b1, const float* __restrict__ b2,
             const float* __restrict__ b3,
             float* __restrict__ out) {
    extern __shared__ uint32_t smw[];
    uint32_t sbyte = smem_u32(smw);

    int tid = threadIdx.x;
    int wid = tid >> 5;
    int lane = tid & 31;
    int g = lane >> 2;
    int t = lane & 3;
    int n0 = wid * 32;
    int n3 = wid * 16;
    long e0 = (long)blockIdx.x * CTA_M;

    uint32_t wb[2] = { sbyte + WOFFW * 4, sbyte + WOFFW * 4 + WSLOTB };
    uint32_t bL12 = sbyte + WOFFW * 4 + (uint32_t)((n0 + ((lane >> 4) & 1) * 8 + (lane & 7)) * 128);
    uint32_t bL3  = sbyte + WOFFW * 4 + (uint32_t)((n3 + ((lane >> 4) & 1) * 8 + (lane & 7)) * 128);

    __shared__ int b64s;
    if (tid == 0) {
        const long long* p = (const long long*)batch;
        int f = 1;
        for (int i = 0; i < 16; i++) { long long v = p[i]; if (v < 0 || v >= 64) f = 0; }
        b64s = f;
    }
    __syncthreads();
    int b64 = b64s;

    // per-thread X source pointers, gather index resolved once (R13)
    int xrow = tid >> 2;
    const float* pseg0 = src  + (e0 + xrow) * 128;
    const float* pseg1 = dstp + (e0 + xrow) * 128;
    const float* pseg2 = ea   + (e0 + xrow) * 128;
    long bi = b64 ? (long)((const long long*)batch)[e0 + xrow]
                  : (long)((const int*)batch)[e0 + xrow];
    const float* pseg3 = u + bi * 128;

    float acc[4][4][4];
#pragma unroll
    for (int a = 0; a < 4; a++)
#pragma unroll
        for (int b = 0; b < 4; b++)
#pragma unroll
            for (int c = 0; c < 4; c++) acc[a][b][c] = 0.0f;

    // ============== Layer 1: K=512 (8 chunks of 64), N=256 (R13) ==========
    {
        float4 xv[4];
        x_ldg(xv, pseg0, 0, tid);
        x_sts(smw, xv, tid);
        stage_w<256, 512>(wb[0], g_W1t, 0, tid);
        CP_COMMIT();
        x_ldg(xv, pseg0, 1, tid);
        x_sts(smw + XSLOTW, xv, tid);
        stage_w<256, 512>(wb[1], g_W1t, 1, tid);
        CP_COMMIT();
    }
#pragma unroll 1
    for (int kc = 0; kc < 8; kc++) {
        int s = kc & 1;
        CP_WAIT1();
        __syncthreads();
        float4 xv[4];
        bool pfx = (kc < 6);
        if (pfx) {
            int kn = kc + 2;
            int seg = kn >> 1;
            const float* p = (seg == 0) ? pseg0 : (seg == 1) ? pseg1
                           : (seg == 2) ? pseg2 : pseg3;
            x_ldg(xv, p, kn, tid);
        }
        gemm64<2>(acc, sbyte + s * (XSLOTW * 4), 128, 0, bL12 + s * WSLOTB, lane);
        __syncthreads();
        if (pfx) {
            x_sts(smw + s * XSLOTW, xv, tid);
            stage_w<256, 512>(wb[s], g_W1t, kc + 2, tid);
        } else {
            stage_w<256, 256>(wb[s], g_W2t, kc - 6, tid);   // W2 chunks 0,1
        }
        CP_COMMIT();
    }
    epi_h<4>(acc, smw, b1, n0, g, t);
    CP_WAIT0();                           // W2 chunks 0,1 complete
    __syncthreads();                      // publish H1 + cp visibility

    // ============== Layer 2: two slot-pair phases, barrier-free gemm pairs ==
#pragma unroll
    for (int a = 0; a < 4; a++)
#pragma unroll
        for (int b = 0; b < 4; b++)
#pragma unroll
            for (int c = 0; c < 4; c++) acc[a][b][c] = 0.0f;

    gemm64<2>(acc, sbyte, 512, 0,  bL12, lane);             // chunk 0 (slot 0)
    gemm64<2>(acc, sbyte, 512, 8,  bL12 + WSLOTB, lane);    // chunk 1 (slot 1)
    __syncthreads();                      // all reads of slots done
    stage_w<256, 256>(wb[0], g_W2t, 2, tid);
    stage_w<256, 256>(wb[1], g_W2t, 3, tid);
    CP_COMMIT();
    CP_WAIT0();
    __syncthreads();
    gemm64<2>(acc, sbyte, 512, 16, bL12, lane);             // chunk 2
    gemm64<2>(acc, sbyte, 512, 24, bL12 + WSLOTB, lane);    // chunk 3
    __syncthreads();                      // slot reads done
    // stage W3 K[0:128] into both slots; overlap with epilogue b2
    stage_w<128, 256>(wb[0], g_W3t, 0, tid);
    stage_w<128, 256>(wb[1], g_W3t, 1, tid);
    CP_COMMIT();
    epi_h<4>(acc, smw, b2, n0, g, t);     // compute overlaps cp.async
    CP_WAIT0();
    __syncthreads();                      // publish H2 + cp visibility

    // ============== Layer 3: two slot-pair phases, N=128 ==================
    float acc3[4][2][4];
#pragma unroll
    for (int a = 0; a < 4; a++)
#pragma unroll
        for (int b = 0; b < 2; b++)
#pragma unroll
            for (int c = 0; c < 4; c++) acc3[a][b][c] = 0.0f;

    gemm64<1>(acc3, sbyte, 512, 0,  bL3, lane);             // chunk 0
    gemm64<1>(acc3, sbyte, 512, 8,  bL3 + WSLOTB, lane);    // chunk 1
    __syncthreads();
    stage_w<128, 256>(wb[0], g_W3t, 2, tid);
    stage_w<128, 256>(wb[1], g_W3t, 3, tid);
    CP_COMMIT();
    CP_WAIT0();
    __syncthreads();
    gemm64<1>(acc3, sbyte, 512, 16, bL3, lane);             // chunk 2
    gemm64<1>(acc3, sbyte, 512, 24, bL3 + WSLOTB, lane);    // chunk 3
    __syncthreads();                      // all H2/W reads done

    // ---- output epilogue: f32 scratch (stride 132 over dead H/W) ----
    float* fH = (float*)smw;
#pragma unroll
    for (int nt = 0; nt < 2; nt++) {
        int c = n3 + nt * 8 + 2 * t;
        float bb0 = __ldg(b3 + c);
        float bb1 = __ldg(b3 + c + 1);
#pragma unroll
        for (int mt = 0; mt < 4; mt++) {
            int r = mt * 16 + g;
            *(float2*)(fH + r * 132 + c) =
                make_float2(acc3[mt][nt][0] + bb0, acc3[mt][nt][1] + bb1);
            *(float2*)(fH + (r + 8) * 132 + c) =
                make_float2(acc3[mt][nt][2] + bb0, acc3[mt][nt][3] + bb1);
        }
    }
    __syncthreads();
#pragma unroll
    for (int it = 0; it < 8; it++) {
        int task = tid + it * THREADS;
        int row = task >> 5, c4 = task & 31;
        *(float4*)(out + (e0 + row) * 128 + c4 * 4) =
            *(const float4*)(fH + row * 132 + c4 * 4);
    }
}

extern "C" void kernel_launch(void* const* d_in, const int* in_sizes, int n_in,
                              void* d_out, int out_size) {
    const float* src  = (const float*)d_in[0];
    const float* dstp = (const float*)d_in[1];
    const float* ea   = (const float*)d_in[2];
    const float* u    = (const float*)d_in[3];
    const void*  bat  = (const void*)d_in[4];
    const float* W1   = (const float*)d_in[5];
    const float* b1   = (const float*)d_in[6];
    const float* W2   = (const float*)d_in[7];
    const float* b2   = (const float*)d_in[8];
    const float* W3   = (const float*)d_in[9];
    const float* b3   = (const float*)d_in[10];
    float* out = (float*)d_out;

    cudaFuncSetAttribute(edge_mlp_v17,
                         cudaFuncAttributeMaxDynamicSharedMemorySize, SMEM_BYTES);

    __half *w1t, *w2t, *w3t;
    cudaGetSymbolAddress((void**)&w1t, g_W1t);
    cudaGetSymbolAddress((void**)&w2t, g_W2t);
    cudaGetSymbolAddress((void**)&w3t, g_W3t);
    dim3 blk(32, 8);
    prep_w<<<dim3(16, 8), blk>>>(W1, w1t, 512, 256);
    prep_w<<<dim3(8, 8),  blk>>>(W2, w2t, 256, 256);
    prep_w<<<dim3(8, 4),  blk>>>(W3, w3t, 256, 128);

    const int n_edges = in_sizes[4];
    const int grid = n_edges / CTA_M;   // 6250
    edge_mlp_v17<<<grid, THREADS, SMEM_BYTES>>>(src, dstp, ea, u, bat,
                                                b1, b2, b3, out);
}